// round 1
// baseline (speedup 1.0000x reference)
#include <cuda_runtime.h>

// Global fp64 accumulator (no device allocation allowed; __device__ global is the
// sanctioned scratch). Zeroed by a tiny kernel at the start of every launch so
// kernel_launch stays deterministic and graph-replayable.
__device__ double g_acc;

__global__ void zero_acc_kernel() {
    g_acc = 0.0;
}

__global__ __launch_bounds__(256)
void giou_reduce_kernel(const float4* __restrict__ pred,
                        const float4* __restrict__ targ,
                        int n) {
    float local = 0.0f;
    const int stride = gridDim.x * blockDim.x;
    for (int i = blockIdx.x * blockDim.x + threadIdx.x; i < n; i += stride) {
        const float4 p = __ldg(pred + i);   // x1,y1,x2,y2
        const float4 t = __ldg(targ + i);

        const float area_p = (p.z - p.x) * (p.w - p.y);
        const float area_t = (t.z - t.x) * (t.w - t.y);

        const float iw = fmaxf(fminf(p.z, t.z) - fmaxf(p.x, t.x), 0.0f);
        const float ih = fmaxf(fminf(p.w, t.w) - fmaxf(p.y, t.y), 0.0f);
        const float inter = iw * ih;
        const float uni = area_p + area_t - inter;
        const float iou = inter / uni;

        const float ew = fmaxf(fmaxf(p.z, t.z) - fminf(p.x, t.x), 0.0f);
        const float eh = fmaxf(fmaxf(p.w, t.w) - fminf(p.y, t.y), 0.0f);
        const float enc = ew * eh;

        const float giou = iou - (enc - uni) / enc;
        local += 1.0f - giou;
    }

    // intra-warp reduce
    #pragma unroll
    for (int off = 16; off > 0; off >>= 1)
        local += __shfl_down_sync(0xffffffffu, local, off);

    __shared__ float warp_sums[8];
    const int lane = threadIdx.x & 31;
    const int wid  = threadIdx.x >> 5;
    if (lane == 0) warp_sums[wid] = local;
    __syncthreads();

    if (wid == 0) {
        local = (lane < (blockDim.x >> 5)) ? warp_sums[lane] : 0.0f;
        #pragma unroll
        for (int off = 4; off > 0; off >>= 1)
            local += __shfl_down_sync(0xffu, local, off);
        if (lane == 0)
            atomicAdd(&g_acc, (double)local);  // one fp64 atomic per block
    }
}

__global__ void finalize_kernel(float* __restrict__ out, double inv_n) {
    out[0] = (float)(g_acc * inv_n);
}

extern "C" void kernel_launch(void* const* d_in, const int* in_sizes, int n_in,
                              void* d_out, int out_size) {
    const float4* pred = (const float4*)d_in[0];
    const float4* targ = (const float4*)d_in[1];
    const int n = in_sizes[0] / 4;   // element count is floats; 4 floats per box

    float* out = (float*)d_out;

    zero_acc_kernel<<<1, 1>>>();

    const int threads = 256;
    int blocks = (n + threads - 1) / threads;
    if (blocks > 2048) blocks = 2048;   // grid-stride; ~15 iters/thread at n=8M
    giou_reduce_kernel<<<blocks, threads>>>(pred, targ, n);

    finalize_kernel<<<1, 1>>>(out, 1.0 / (double)n);
}